// round 3
// baseline (speedup 1.0000x reference)
#include <cuda_runtime.h>
#include <math.h>

// Problem constants
#define B_   8
#define T_   4
#define C_   512
#define H_   32
#define W_   32
#define HW_  1024
#define BT_  32          // B_*T_
#define TC_  2048        // T_*C_
#define KSPLIT 32
#define CPB  (C_/KSPLIT) // 16 channels per block
#define HP_  28
#define WP_  28
#define NP_  784         // 28*28
#define BN_EPS 1e-5
#define BSTRIDE ((size_t)T_ * C_ * HW_)   // elements between consecutive b

// Scratch (allocation-free rule: __device__ globals)
__device__ float g_A[TC_];
__device__ float g_B[TC_];
__device__ float g_D[TC_];
__device__ float g_part[KSPLIT][BT_ * HW_];

// ---------------------------------------------------------------------------
// Kernel 1 (per t-chunk): per-c stats for left and right -> A, B, D coeffs.
// grid: 512 blocks (c), 256 threads. Each block reads 32KB/tensor (8 b-slices
// of 4KB). Warp-shuffle reduction + tiny double combine.
// ---------------------------------------------------------------------------
__global__ __launch_bounds__(256) void stats_kernel(
    const float* __restrict__ l, const float* __restrict__ r,
    const float* __restrict__ gamma, int t)
{
    const int c   = blockIdx.x;
    const int tc  = t * C_ + c;
    const int tid = threadIdx.x;

    const size_t base = ((size_t)tc) * HW_ + (size_t)tid * 4;

    float sl = 0.f, ql = 0.f, sr = 0.f, qr = 0.f;
    #pragma unroll
    for (int b = 0; b < B_; b++) {
        float4 lv = *reinterpret_cast<const float4*>(l + base + (size_t)b * BSTRIDE);
        float4 rv = *reinterpret_cast<const float4*>(r + base + (size_t)b * BSTRIDE);
        sl += lv.x + lv.y + lv.z + lv.w;
        ql = fmaf(lv.x, lv.x, ql); ql = fmaf(lv.y, lv.y, ql);
        ql = fmaf(lv.z, lv.z, ql); ql = fmaf(lv.w, lv.w, ql);
        sr += rv.x + rv.y + rv.z + rv.w;
        qr = fmaf(rv.x, rv.x, qr); qr = fmaf(rv.y, rv.y, qr);
        qr = fmaf(rv.z, rv.z, qr); qr = fmaf(rv.w, rv.w, qr);
    }

    // warp-level float reduction
    #pragma unroll
    for (int o = 16; o > 0; o >>= 1) {
        sl += __shfl_xor_sync(0xffffffffu, sl, o);
        ql += __shfl_xor_sync(0xffffffffu, ql, o);
        sr += __shfl_xor_sync(0xffffffffu, sr, o);
        qr += __shfl_xor_sync(0xffffffffu, qr, o);
    }

    __shared__ float w0[8], w1[8], w2[8], w3[8];
    const int wid  = tid >> 5;
    const int lane = tid & 31;
    if (lane == 0) { w0[wid] = sl; w1[wid] = ql; w2[wid] = sr; w3[wid] = qr; }
    __syncthreads();

    if (tid == 0) {
        double S0 = 0, S1 = 0, S2 = 0, S3 = 0;
        #pragma unroll
        for (int k = 0; k < 8; k++) {
            S0 += (double)w0[k]; S1 += (double)w1[k];
            S2 += (double)w2[k]; S3 += (double)w3[k];
        }
        const double n = (double)(B_ * HW_);   // 8192
        double mul = S0 / n;
        double mur = S2 / n;
        double varl = S1 / n - mul * mul;
        double varr = S3 / n - mur * mur;
        double invl = 1.0 / sqrt(varl + BN_EPS);
        double invr = 1.0 / sqrt(varr + BN_EPS);
        double g = (double)gamma[c];
        double A = g * invl;
        double Bc = g * invr;
        g_A[tc] = (float)A;
        g_B[tc] = (float)Bc;
        g_D[tc] = (float)(A * mul - Bc * mur);
    }
}

// ---------------------------------------------------------------------------
// Kernel 2 (per t-chunk): diff2 partials. grid: 8 (b) x 32 channel-splits
// = 256 blocks, 1024 threads. Runs right after stats(t): reads are L2-hot.
// ---------------------------------------------------------------------------
__global__ __launch_bounds__(1024) void diff2_kernel(
    const float* __restrict__ l, const float* __restrict__ r, int t)
{
    const int b    = blockIdx.x >> 5;        // /KSPLIT
    const int part = blockIdx.x & (KSPLIT-1);
    const int hw   = threadIdx.x;            // 0..1023
    const int bt   = b * T_ + t;

    __shared__ float sA[CPB], sB[CPB], sD[CPB];
    if (hw < CPB) {
        int tc = t * C_ + part * CPB + hw;
        sA[hw] = g_A[tc];
        sB[hw] = g_B[tc];
        sD[hw] = g_D[tc];
    }
    __syncthreads();

    const float* lp = l + ((size_t)(bt * C_ + part * CPB)) * HW_ + hw;
    const float* rp = r + ((size_t)(bt * C_ + part * CPB)) * HW_ + hw;

    float acc = 0.f;
    #pragma unroll
    for (int i = 0; i < CPB; i++) {
        float d = sA[i] * lp[(size_t)i * HW_] - sB[i] * rp[(size_t)i * HW_] - sD[i];
        acc = fmaf(d, d, acc);
    }
    g_part[part][bt * HW_ + hw] = acc;
}

// ---------------------------------------------------------------------------
// Kernel 3: sum partials, 5x5 window sum, sqrt, max + first-argmin.
// grid: 32 blocks (one per (b,t)), 1024 threads.
// Output layout (float32, tuple order):
//   [0,32) values (B,T) | [32,96) coords (B,T,2) [x,y] | [96,25184) heatmap
// ---------------------------------------------------------------------------
__global__ __launch_bounds__(1024) void finalize_kernel(float* __restrict__ out)
{
    const int bt  = blockIdx.x;
    const int tid = threadIdx.x;

    __shared__ float d2[HW_];
    {
        float s = 0.f;
        #pragma unroll
        for (int k = 0; k < KSPLIT; k++) s += g_part[k][bt * HW_ + tid];
        d2[tid] = s;
    }
    __syncthreads();

    float mymax = -3.0e38f;
    float mymin =  3.0e38f;
    int   myidx = 0x7fffffff;

    if (tid < NP_) {
        const int y = tid / WP_;
        const int x = tid % WP_;
        float ws = 0.f;
        #pragma unroll
        for (int dy = 0; dy < 5; dy++)
            #pragma unroll
            for (int dx = 0; dx < 5; dx++)
                ws += d2[(y + dy) * W_ + (x + dx)];
        float hm = sqrtf(ws / 25.0f);
        out[96 + bt * NP_ + tid] = hm;
        mymax = hm; mymin = hm; myidx = tid;
    }

    __shared__ float smx[1024];
    __shared__ float smn[1024];
    __shared__ int   six[1024];
    smx[tid] = mymax; smn[tid] = mymin; six[tid] = myidx;
    __syncthreads();
    for (int st = 512; st > 0; st >>= 1) {
        if (tid < st) {
            smx[tid] = fmaxf(smx[tid], smx[tid + st]);
            float v = smn[tid + st];
            int  ix = six[tid + st];
            if (v < smn[tid] || (v == smn[tid] && ix < six[tid])) {
                smn[tid] = v; six[tid] = ix;
            }
        }
        __syncthreads();
    }

    if (tid == 0) {
        out[bt] = smx[0];
        int idx = six[0];
        out[32 + bt * 2 + 0] = (float)(idx % WP_);  // x_argmin
        out[32 + bt * 2 + 1] = (float)(idx / WP_);  // y_argmin
    }
}

// ---------------------------------------------------------------------------
// Schedule: t-chunked. Stream 0 runs the 4 DRAM-bound stats chunks
// back-to-back; a forked stream runs each L2-hot diff2 chunk as soon as its
// stats chunk is done, overlapping with the next chunk's stats. Finalize
// joins. Fork/join via events is graph-capture legal (fork pattern).
// ---------------------------------------------------------------------------
extern "C" void kernel_launch(void* const* d_in, const int* in_sizes, int n_in,
                              void* d_out, int out_size)
{
    const float* l     = (const float*)d_in[0];
    const float* r     = (const float*)d_in[1];
    const float* gamma = (const float*)d_in[2];
    // d_in[3] = bn_beta: cancels exactly in (l_bn - r_bn), unused.
    float* out = (float*)d_out;

    static cudaStream_t s2 = nullptr;
    static cudaEvent_t evS[T_];
    static cudaEvent_t evD = nullptr;
    if (s2 == nullptr) {
        cudaStreamCreateWithFlags(&s2, cudaStreamNonBlocking);
        for (int t = 0; t < T_; t++)
            cudaEventCreateWithFlags(&evS[t], cudaEventDisableTiming);
        cudaEventCreateWithFlags(&evD, cudaEventDisableTiming);
    }

    for (int t = 0; t < T_; t++) {
        stats_kernel<<<C_, 256>>>(l, r, gamma, t);
        cudaEventRecord(evS[t], 0);
        cudaStreamWaitEvent(s2, evS[t], 0);
        diff2_kernel<<<B_ * KSPLIT, 1024, 0, s2>>>(l, r, t);
    }
    cudaEventRecord(evD, s2);
    cudaStreamWaitEvent(0, evD, 0);
    finalize_kernel<<<BT_, 1024>>>(out);
}

// round 4
// speedup vs baseline: 1.6044x; 1.6044x over previous
#include <cuda_runtime.h>
#include <math.h>

// Problem constants
#define B_   8
#define T_   4
#define C_   512
#define H_   32
#define W_   32
#define HW_  1024
#define BT_  32          // B_*T_
#define TC_  2048        // T_*C_
#define NPART 64         // channel partitions per t
#define CPP   (C_/NPART) // 8 channels per block
#define HP_  28
#define WP_  28
#define NP_  784         // 28*28
#define BN_EPS 1e-5f
#define BSTRIDE ((size_t)T_ * C_ * HW_)   // elements between consecutive b

// Scratch (allocation-free rule: __device__ globals)
__device__ float g_part[NPART][BT_ * HW_];   // 8 MB

// ---------------------------------------------------------------------------
// Fused kernel: ONE pass over the tensors.
// grid: T_*NPART = 256 blocks (2/SM, single wave), 1024 threads.
// Block (t,p) owns channels c in [p*8, p*8+8). Per channel:
//   - each thread loads 2 float4 of l and 2 of r (8 scalars each) -> registers
//   - block-wide reduction of (sum, sumsq) for both tensors
//   - warp 0 computes A = g*rsqrt(var_l+eps), B = g*rsqrt(var_r+eps),
//     D = A*mu_l - B*mu_r   (beta cancels in l_bn - r_bn)
//   - every thread computes d = A*lv - B*rv - D from its REGISTERS and
//     accumulates d^2 into 8 per-thread register accumulators
// After 8 channels, write the 8192 d^2 partials for this (t,p).
// ---------------------------------------------------------------------------
__global__ __launch_bounds__(1024, 2) void fused_kernel(
    const float* __restrict__ l, const float* __restrict__ r,
    const float* __restrict__ gamma)
{
    const int t   = blockIdx.x >> 6;        // / NPART
    const int p   = blockIdx.x & (NPART-1);
    const int tid = threadIdx.x;
    const int lane = tid & 31;
    const int wid  = tid >> 5;

    // float4-index mapping: f4idx in [0,2048): b = f4idx>>8, hw4 = f4idx&255
    const int f4a = tid;            // first float4 slot
    const int f4b = tid + 1024;     // second float4 slot
    const int ba = f4a >> 8, ra_ = f4a & 255;
    const int bb = f4b >> 8, rb_ = f4b & 255;

    __shared__ float w0[32], w1[32], w2[32], w3[32];
    __shared__ float sco[3];              // A, B, D broadcast
    __shared__ float sgamma[CPP];

    if (tid < CPP) sgamma[tid] = gamma[p * CPP + tid];

    float acc[8];
    #pragma unroll
    for (int k = 0; k < 8; k++) acc[k] = 0.f;

    const float4* l4 = reinterpret_cast<const float4*>(l);
    const float4* r4 = reinterpret_cast<const float4*>(r);

    #pragma unroll 1
    for (int ci = 0; ci < CPP; ci++) {
        const int c = p * CPP + ci;
        const size_t base4 = ((size_t)(t * C_ + c)) * (HW_ / 4);

        // ---- load 8 l + 8 r scalars into registers (4 independent LDG.128)
        float4 lva = l4[(size_t)ba * (BSTRIDE/4) + base4 + ra_];
        float4 lvb = l4[(size_t)bb * (BSTRIDE/4) + base4 + rb_];
        float4 rva = r4[(size_t)ba * (BSTRIDE/4) + base4 + ra_];
        float4 rvb = r4[(size_t)bb * (BSTRIDE/4) + base4 + rb_];

        // ---- per-thread partial sums
        float sl = (lva.x + lva.y) + (lva.z + lva.w)
                 + (lvb.x + lvb.y) + (lvb.z + lvb.w);
        float sr = (rva.x + rva.y) + (rva.z + rva.w)
                 + (rvb.x + rvb.y) + (rvb.z + rvb.w);
        float ql = 0.f, qr = 0.f;
        ql = fmaf(lva.x, lva.x, ql); ql = fmaf(lva.y, lva.y, ql);
        ql = fmaf(lva.z, lva.z, ql); ql = fmaf(lva.w, lva.w, ql);
        ql = fmaf(lvb.x, lvb.x, ql); ql = fmaf(lvb.y, lvb.y, ql);
        ql = fmaf(lvb.z, lvb.z, ql); ql = fmaf(lvb.w, lvb.w, ql);
        qr = fmaf(rva.x, rva.x, qr); qr = fmaf(rva.y, rva.y, qr);
        qr = fmaf(rva.z, rva.z, qr); qr = fmaf(rva.w, rva.w, qr);
        qr = fmaf(rvb.x, rvb.x, qr); qr = fmaf(rvb.y, rvb.y, qr);
        qr = fmaf(rvb.z, rvb.z, qr); qr = fmaf(rvb.w, rvb.w, qr);

        // ---- warp reduce 4 values
        #pragma unroll
        for (int o = 16; o > 0; o >>= 1) {
            sl += __shfl_xor_sync(0xffffffffu, sl, o);
            ql += __shfl_xor_sync(0xffffffffu, ql, o);
            sr += __shfl_xor_sync(0xffffffffu, sr, o);
            qr += __shfl_xor_sync(0xffffffffu, qr, o);
        }
        if (lane == 0) { w0[wid] = sl; w1[wid] = ql; w2[wid] = sr; w3[wid] = qr; }
        __syncthreads();

        // ---- warp 0 combines 32 warp-sums, computes coefficients
        if (wid == 0) {
            float a0 = w0[lane], a1 = w1[lane], a2 = w2[lane], a3 = w3[lane];
            #pragma unroll
            for (int o = 16; o > 0; o >>= 1) {
                a0 += __shfl_xor_sync(0xffffffffu, a0, o);
                a1 += __shfl_xor_sync(0xffffffffu, a1, o);
                a2 += __shfl_xor_sync(0xffffffffu, a2, o);
                a3 += __shfl_xor_sync(0xffffffffu, a3, o);
            }
            if (lane == 0) {
                const float inv_n = 1.f / (float)(B_ * HW_);   // 1/8192
                float mul  = a0 * inv_n;
                float mur  = a2 * inv_n;
                float varl = fmaf(-mul, mul, a1 * inv_n);
                float varr = fmaf(-mur, mur, a3 * inv_n);
                float invl = 1.f / sqrtf(varl + BN_EPS);
                float invr = 1.f / sqrtf(varr + BN_EPS);
                float g  = sgamma[ci];
                float A  = g * invl;
                float Bc = g * invr;
                sco[0] = A;
                sco[1] = Bc;
                sco[2] = A * mul - Bc * mur;
            }
        }
        __syncthreads();

        // ---- accumulate d^2 straight from registers
        const float A = sco[0], Bc = sco[1], D = sco[2];
        float d;
        d = A*lva.x - Bc*rva.x - D; acc[0] = fmaf(d, d, acc[0]);
        d = A*lva.y - Bc*rva.y - D; acc[1] = fmaf(d, d, acc[1]);
        d = A*lva.z - Bc*rva.z - D; acc[2] = fmaf(d, d, acc[2]);
        d = A*lva.w - Bc*rva.w - D; acc[3] = fmaf(d, d, acc[3]);
        d = A*lvb.x - Bc*rvb.x - D; acc[4] = fmaf(d, d, acc[4]);
        d = A*lvb.y - Bc*rvb.y - D; acc[5] = fmaf(d, d, acc[5]);
        d = A*lvb.z - Bc*rvb.z - D; acc[6] = fmaf(d, d, acc[6]);
        d = A*lvb.w - Bc*rvb.w - D; acc[7] = fmaf(d, d, acc[7]);
        __syncthreads();   // protect sco before next iteration overwrites
    }

    // ---- write partials: position (b, hw) -> g_part[p][(b*T+t)*1024 + hw]
    float4 o0 = make_float4(acc[0], acc[1], acc[2], acc[3]);
    float4 o1 = make_float4(acc[4], acc[5], acc[6], acc[7]);
    float4* gp = reinterpret_cast<float4*>(g_part[p]);
    gp[(ba * T_ + t) * (HW_/4) + ra_] = o0;
    gp[(bb * T_ + t) * (HW_/4) + rb_] = o1;
}

// ---------------------------------------------------------------------------
// Finalize: sum 64 partials, 5x5 window sum, sqrt, max + first-argmin.
// grid: 32 blocks (one per (b,t)), 1024 threads.
// Output layout (float32, tuple order):
//   [0,32) values (B,T) | [32,96) coords (B,T,2) [x,y] | [96,25184) heatmap
// ---------------------------------------------------------------------------
__global__ __launch_bounds__(1024) void finalize_kernel(float* __restrict__ out)
{
    const int bt  = blockIdx.x;
    const int tid = threadIdx.x;

    __shared__ float d2[HW_];
    {
        float s = 0.f;
        #pragma unroll
        for (int k = 0; k < NPART; k++) s += g_part[k][bt * HW_ + tid];
        d2[tid] = s;
    }
    __syncthreads();

    float mymax = -3.0e38f;
    float mymin =  3.0e38f;
    int   myidx = 0x7fffffff;

    if (tid < NP_) {
        const int y = tid / WP_;
        const int x = tid % WP_;
        float ws = 0.f;
        #pragma unroll
        for (int dy = 0; dy < 5; dy++)
            #pragma unroll
            for (int dx = 0; dx < 5; dx++)
                ws += d2[(y + dy) * W_ + (x + dx)];
        float hm = sqrtf(ws / 25.0f);
        out[96 + bt * NP_ + tid] = hm;
        mymax = hm; mymin = hm; myidx = tid;
    }

    __shared__ float smx[1024];
    __shared__ float smn[1024];
    __shared__ int   six[1024];
    smx[tid] = mymax; smn[tid] = mymin; six[tid] = myidx;
    __syncthreads();
    for (int st = 512; st > 0; st >>= 1) {
        if (tid < st) {
            smx[tid] = fmaxf(smx[tid], smx[tid + st]);
            float v = smn[tid + st];
            int  ix = six[tid + st];
            if (v < smn[tid] || (v == smn[tid] && ix < six[tid])) {
                smn[tid] = v; six[tid] = ix;
            }
        }
        __syncthreads();
    }

    if (tid == 0) {
        out[bt] = smx[0];
        int idx = six[0];
        out[32 + bt * 2 + 0] = (float)(idx % WP_);  // x_argmin
        out[32 + bt * 2 + 1] = (float)(idx / WP_);  // y_argmin
    }
}

// ---------------------------------------------------------------------------
extern "C" void kernel_launch(void* const* d_in, const int* in_sizes, int n_in,
                              void* d_out, int out_size)
{
    const float* l     = (const float*)d_in[0];
    const float* r     = (const float*)d_in[1];
    const float* gamma = (const float*)d_in[2];
    // d_in[3] = bn_beta: cancels exactly in (l_bn - r_bn), unused.
    float* out = (float*)d_out;

    fused_kernel<<<T_ * NPART, 1024>>>(l, r, gamma);
    finalize_kernel<<<BT_, 1024>>>(out);
}

// round 5
// speedup vs baseline: 1.7711x; 1.1039x over previous
#include <cuda_runtime.h>
#include <math.h>

// Problem constants
#define B_   8
#define T_   4
#define C_   512
#define H_   32
#define W_   32
#define HW_  1024
#define BT_  32          // B_*T_
#define NPART 32         // channel partitions per t
#define CPP   (C_/NPART) // 16 channels per block
#define HP_  28
#define WP_  28
#define NP_  784         // 28*28
#define BN_EPS 1e-5f
#define BSTRIDE ((size_t)T_ * C_ * HW_)   // elements between consecutive b

// Scratch (allocation-free rule: __device__ globals)
__device__ float g_part[NPART][BT_ * HW_];   // 4 MB
__device__ float g_d2[BT_ * HW_];            // 128 KB

// ---------------------------------------------------------------------------
// Fused kernel: ONE pass over the tensors, software-pipelined over channels.
// grid: T_*NPART = 128 blocks (1/SM, single wave), 1024 threads, ~52 regs.
// Block (t,p) owns 16 channels. Per channel:
//   prefetch next channel's 4x LDG.128 -> reduce current (sum,sumsq both
//   tensors) -> A,B,D coefficients -> accumulate d^2 from registers.
// beta cancels exactly in (l_bn - r_bn).
// ---------------------------------------------------------------------------
__global__ __launch_bounds__(1024, 1) void fused_kernel(
    const float* __restrict__ l, const float* __restrict__ r,
    const float* __restrict__ gamma)
{
    const int t   = blockIdx.x >> 5;        // / NPART
    const int p   = blockIdx.x & (NPART-1);
    const int tid = threadIdx.x;
    const int lane = tid & 31;
    const int wid  = tid >> 5;

    // float4-slot mapping: slot in [0,2048): b = slot>>8, hw4 = slot&255
    const int ba = tid >> 8,          ra_ = tid & 255;          // slots 0..1023
    const int bb = (tid + 1024) >> 8, rb_ = tid & 255;          // slots 1024..2047

    __shared__ float w0[32], w1[32], w2[32], w3[32];
    __shared__ float sco[3];              // A, B, D broadcast
    __shared__ float sgamma[CPP];
    if (tid < CPP) sgamma[tid] = gamma[p * CPP + tid];

    float acc[8];
    #pragma unroll
    for (int k = 0; k < 8; k++) acc[k] = 0.f;

    const float4* l4 = reinterpret_cast<const float4*>(l);
    const float4* r4 = reinterpret_cast<const float4*>(r);
    const size_t offA = (size_t)ba * (BSTRIDE/4) + ra_;
    const size_t offB = (size_t)bb * (BSTRIDE/4) + rb_;
    const size_t ch0  = ((size_t)(t * C_ + p * CPP)) * (HW_/4);

    // prologue: load channel 0
    float4 lva = l4[offA + ch0];
    float4 lvb = l4[offB + ch0];
    float4 rva = r4[offA + ch0];
    float4 rvb = r4[offB + ch0];

    #pragma unroll
    for (int ci = 0; ci < CPP; ci++) {
        // ---- prefetch next channel (overlaps the reduction below)
        float4 nl_a, nl_b, nr_a, nr_b;
        if (ci < CPP - 1) {
            const size_t chn = ch0 + (size_t)(ci + 1) * (HW_/4);
            nl_a = l4[offA + chn];
            nl_b = l4[offB + chn];
            nr_a = r4[offA + chn];
            nr_b = r4[offB + chn];
        }

        // ---- per-thread partial sums for current channel
        float sl = (lva.x + lva.y) + (lva.z + lva.w)
                 + (lvb.x + lvb.y) + (lvb.z + lvb.w);
        float sr = (rva.x + rva.y) + (rva.z + rva.w)
                 + (rvb.x + rvb.y) + (rvb.z + rvb.w);
        float ql = 0.f, qr = 0.f;
        ql = fmaf(lva.x, lva.x, ql); ql = fmaf(lva.y, lva.y, ql);
        ql = fmaf(lva.z, lva.z, ql); ql = fmaf(lva.w, lva.w, ql);
        ql = fmaf(lvb.x, lvb.x, ql); ql = fmaf(lvb.y, lvb.y, ql);
        ql = fmaf(lvb.z, lvb.z, ql); ql = fmaf(lvb.w, lvb.w, ql);
        qr = fmaf(rva.x, rva.x, qr); qr = fmaf(rva.y, rva.y, qr);
        qr = fmaf(rva.z, rva.z, qr); qr = fmaf(rva.w, rva.w, qr);
        qr = fmaf(rvb.x, rvb.x, qr); qr = fmaf(rvb.y, rvb.y, qr);
        qr = fmaf(rvb.z, rvb.z, qr); qr = fmaf(rvb.w, rvb.w, qr);

        #pragma unroll
        for (int o = 16; o > 0; o >>= 1) {
            sl += __shfl_xor_sync(0xffffffffu, sl, o);
            ql += __shfl_xor_sync(0xffffffffu, ql, o);
            sr += __shfl_xor_sync(0xffffffffu, sr, o);
            qr += __shfl_xor_sync(0xffffffffu, qr, o);
        }
        if (lane == 0) { w0[wid] = sl; w1[wid] = ql; w2[wid] = sr; w3[wid] = qr; }
        __syncthreads();

        if (wid == 0) {
            float a0 = w0[lane], a1 = w1[lane], a2 = w2[lane], a3 = w3[lane];
            #pragma unroll
            for (int o = 16; o > 0; o >>= 1) {
                a0 += __shfl_xor_sync(0xffffffffu, a0, o);
                a1 += __shfl_xor_sync(0xffffffffu, a1, o);
                a2 += __shfl_xor_sync(0xffffffffu, a2, o);
                a3 += __shfl_xor_sync(0xffffffffu, a3, o);
            }
            if (lane == 0) {
                const float inv_n = 1.f / (float)(B_ * HW_);   // 1/8192
                float mul  = a0 * inv_n;
                float mur  = a2 * inv_n;
                float varl = fmaf(-mul, mul, a1 * inv_n);
                float varr = fmaf(-mur, mur, a3 * inv_n);
                float invl = 1.f / sqrtf(varl + BN_EPS);
                float invr = 1.f / sqrtf(varr + BN_EPS);
                float g  = sgamma[ci];
                float A  = g * invl;
                float Bc = g * invr;
                sco[0] = A;
                sco[1] = Bc;
                sco[2] = A * mul - Bc * mur;
            }
        }
        __syncthreads();

        // ---- accumulate d^2 straight from registers
        const float A = sco[0], Bc = sco[1], D = sco[2];
        float d;
        d = A*lva.x - Bc*rva.x - D; acc[0] = fmaf(d, d, acc[0]);
        d = A*lva.y - Bc*rva.y - D; acc[1] = fmaf(d, d, acc[1]);
        d = A*lva.z - Bc*rva.z - D; acc[2] = fmaf(d, d, acc[2]);
        d = A*lva.w - Bc*rva.w - D; acc[3] = fmaf(d, d, acc[3]);
        d = A*lvb.x - Bc*rvb.x - D; acc[4] = fmaf(d, d, acc[4]);
        d = A*lvb.y - Bc*rvb.y - D; acc[5] = fmaf(d, d, acc[5]);
        d = A*lvb.z - Bc*rvb.z - D; acc[6] = fmaf(d, d, acc[6]);
        d = A*lvb.w - Bc*rvb.w - D; acc[7] = fmaf(d, d, acc[7]);

        // barrier protecting sco/wsum reuse next iteration is the one at the
        // top of the next iteration's reduction (w* writes happen after the
        // shuffles); need explicit barrier so w* of next iter don't race the
        // warp0 reads of this iter:
        __syncthreads();

        // rotate pipeline registers
        if (ci < CPP - 1) {
            lva = nl_a; lvb = nl_b; rva = nr_a; rvb = nr_b;
        }
    }

    // ---- write partials: g_part[p][(b*T+t)*1024 + hw] as float4
    float4* gp = reinterpret_cast<float4*>(g_part[p]);
    gp[(ba * T_ + t) * (HW_/4) + ra_] = make_float4(acc[0], acc[1], acc[2], acc[3]);
    gp[(bb * T_ + t) * (HW_/4) + rb_] = make_float4(acc[4], acc[5], acc[6], acc[7]);
}

// ---------------------------------------------------------------------------
// Reduce: collapse 32 partials -> g_d2. grid: 256 blocks (bt x 8 segments),
// 1024 threads as (kg = tid>>7 in [0,8), hw_local = tid&127). Each thread
// sums 4 partials; smem combine of 8 groups. Whole 4MB read spread chip-wide.
// ---------------------------------------------------------------------------
__global__ __launch_bounds__(1024) void reduce_kernel()
{
    const int bt = blockIdx.x >> 3;
    const int q  = blockIdx.x & 7;
    const int hw_local = threadIdx.x & 127;
    const int kg = threadIdx.x >> 7;          // 0..7
    const int hw = q * 128 + hw_local;

    float s = 0.f;
    #pragma unroll
    for (int i = 0; i < 4; i++)
        s += g_part[kg * 4 + i][bt * HW_ + hw];

    __shared__ float red[8][128];
    red[kg][hw_local] = s;
    __syncthreads();

    if (kg == 0) {
        float tot = 0.f;
        #pragma unroll
        for (int k = 0; k < 8; k++) tot += red[k][hw_local];
        g_d2[bt * HW_ + hw] = tot;
    }
}

// ---------------------------------------------------------------------------
// Finalize: 5x5 window sum, sqrt, max + first-argmin.
// grid: 32 blocks (one per (b,t)), 1024 threads.
// Output layout (float32, tuple order):
//   [0,32) values (B,T) | [32,96) coords (B,T,2) [x,y] | [96,25184) heatmap
// ---------------------------------------------------------------------------
__global__ __launch_bounds__(1024) void finalize_kernel(float* __restrict__ out)
{
    const int bt  = blockIdx.x;
    const int tid = threadIdx.x;

    __shared__ float d2[HW_];
    d2[tid] = g_d2[bt * HW_ + tid];
    __syncthreads();

    float mymax = -3.0e38f;
    float mymin =  3.0e38f;
    int   myidx = 0x7fffffff;

    if (tid < NP_) {
        const int y = tid / WP_;
        const int x = tid % WP_;
        float ws = 0.f;
        #pragma unroll
        for (int dy = 0; dy < 5; dy++)
            #pragma unroll
            for (int dx = 0; dx < 5; dx++)
                ws += d2[(y + dy) * W_ + (x + dx)];
        float hm = sqrtf(ws / 25.0f);
        out[96 + bt * NP_ + tid] = hm;
        mymax = hm; mymin = hm; myidx = tid;
    }

    __shared__ float smx[1024];
    __shared__ float smn[1024];
    __shared__ int   six[1024];
    smx[tid] = mymax; smn[tid] = mymin; six[tid] = myidx;
    __syncthreads();
    for (int st = 512; st > 0; st >>= 1) {
        if (tid < st) {
            smx[tid] = fmaxf(smx[tid], smx[tid + st]);
            float v = smn[tid + st];
            int  ix = six[tid + st];
            if (v < smn[tid] || (v == smn[tid] && ix < six[tid])) {
                smn[tid] = v; six[tid] = ix;
            }
        }
        __syncthreads();
    }

    if (tid == 0) {
        out[bt] = smx[0];
        int idx = six[0];
        out[32 + bt * 2 + 0] = (float)(idx % WP_);  // x_argmin
        out[32 + bt * 2 + 1] = (float)(idx / WP_);  // y_argmin
    }
}

// ---------------------------------------------------------------------------
extern "C" void kernel_launch(void* const* d_in, const int* in_sizes, int n_in,
                              void* d_out, int out_size)
{
    const float* l     = (const float*)d_in[0];
    const float* r     = (const float*)d_in[1];
    const float* gamma = (const float*)d_in[2];
    // d_in[3] = bn_beta: cancels exactly in (l_bn - r_bn), unused.
    float* out = (float*)d_out;

    fused_kernel<<<T_ * NPART, 1024>>>(l, r, gamma);
    reduce_kernel<<<BT_ * 8, 1024>>>();
    finalize_kernel<<<BT_, 1024>>>(out);
}